// round 13
// baseline (speedup 1.0000x reference)
#include <cuda_runtime.h>
#include <cuda_bf16.h>
#include <cuda_fp16.h>
#include <cstdint>

#define N_NODES 100000
#define N_EDGES 1600000
#define D 128
#define K2 256   // 2*D
#define NBLK 98  // ceil(N_NODES / 1024)
#define E4 (N_EDGES / 4)   // 400000

// Scratch (no device mallocs allowed)
__device__ __half2 g_h16[(size_t)N_NODES * (D / 2)];  // fp16 h (25.6 MB)
__device__ __half2 g_c16[(size_t)N_NODES * (D / 2)];  // fp16 c (25.6 MB)
__device__ int   g_deg[N_NODES];
__device__ int   g_rank[N_EDGES];
__device__ int   g_rowstart[N_NODES];
__device__ int   g_bsum[128];
__device__ int   g_csr[N_EDGES];
__device__ __half g_Wf[D * K2];                // W fp16 [n][k], full K

// ===========================================================================
// Helpers
// ===========================================================================
__device__ __forceinline__ uint32_t smem_u32(const void* p) {
    uint32_t a;
    asm("{ .reg .u64 t; cvta.to.shared.u64 t, %1; cvt.u32.u64 %0, t; }"
        : "=r"(a) : "l"(p));
    return a;
}
#define SW128(o) ((o) ^ (((o) >> 3) & 0x70))

__device__ __forceinline__ void ldsm_x4(uint32_t* r, uint32_t addr) {
    asm volatile("ldmatrix.sync.aligned.m8n8.x4.shared.b16 {%0,%1,%2,%3}, [%4];"
                 : "=r"(r[0]), "=r"(r[1]), "=r"(r[2]), "=r"(r[3]) : "r"(addr));
}
__device__ __forceinline__ void mma_f16(float* c, const uint32_t* a,
                                        uint32_t b0, uint32_t b1) {
    asm volatile(
        "mma.sync.aligned.m16n8k16.row.col.f32.f16.f16.f32 "
        "{%0,%1,%2,%3}, {%4,%5,%6,%7}, {%8,%9}, {%0,%1,%2,%3};"
        : "+f"(c[0]), "+f"(c[1]), "+f"(c[2]), "+f"(c[3])
        : "r"(a[0]), "r"(a[1]), "r"(a[2]), "r"(a[3]), "r"(b0), "r"(b1));
}

// ---------------------------------------------------------------------------
// Fused prep + histogram. Block ranges:
//   [0,128)      : W -> fp16
//   [128,1728)   : h -> fp16
//   [1728,3291)  : edge histogram (4 edges/thread, int4) + rank record
// ---------------------------------------------------------------------------
__global__ void prep_hist(const float* __restrict__ W,
                          const float* __restrict__ h,
                          const int* __restrict__ edst) {
    int b = blockIdx.x;
    int t = threadIdx.x;
    if (b < 128) {
        int i = b * 256 + t;                       // 0..32767
        g_Wf[i] = __float2half(W[i]);
    } else if (b < 1728) {
        int i = (b - 128) * 256 + t;               // float4 index
        int stride = 1600 * 256;
        const int total = N_NODES * (D / 4);       // 3.2M
        for (; i < total; i += stride) {
            float4 v = *(const float4*)(h + (size_t)i * 4);
            __half2 a = __floats2half2_rn(v.x, v.y);
            __half2 c = __floats2half2_rn(v.z, v.w);
            uint2 u;
            u.x = *reinterpret_cast<uint32_t*>(&a);
            u.y = *reinterpret_cast<uint32_t*>(&c);
            *(uint2*)(g_h16 + (size_t)i * 2) = u;
        }
    } else {
        int gi = (b - 1728) * 256 + t;             // int4 edge-group index
        if (gi < E4) {
            int4 d4 = ((const int4*)edst)[gi];
            int4 r4;
            r4.x = atomicAdd(&g_deg[d4.x], 1);
            r4.y = atomicAdd(&g_deg[d4.y], 1);
            r4.z = atomicAdd(&g_deg[d4.z], 1);
            r4.w = atomicAdd(&g_deg[d4.w], 1);
            ((int4*)g_rank)[gi] = r4;
        }
    }
}

// ---------------------------------------------------------------------------
// Scans
// ---------------------------------------------------------------------------
__global__ void scan_blocks() {
    __shared__ int wsum[32];
    int t = threadIdx.x, b = blockIdx.x;
    int i = b * 1024 + t;
    int v = (i < N_NODES) ? g_deg[i] : 0;
    int x = v;
#pragma unroll
    for (int o = 1; o < 32; o <<= 1) {
        int y = __shfl_up_sync(~0u, x, o);
        if ((t & 31) >= o) x += y;
    }
    if ((t & 31) == 31) wsum[t >> 5] = x;
    __syncthreads();
    if (t < 32) {
        int s = wsum[t];
#pragma unroll
        for (int o = 1; o < 32; o <<= 1) {
            int y = __shfl_up_sync(~0u, s, o);
            if (t >= o) s += y;
        }
        wsum[t] = s;
    }
    __syncthreads();
    int off = (t >= 32) ? wsum[(t >> 5) - 1] : 0;
    int incl = x + off;
    if (i < N_NODES) g_rowstart[i] = incl - v;
    if (t == 1023) g_bsum[b] = incl;
}

__global__ void scan_top() {
    __shared__ int s[128];
    int t = threadIdx.x;
    int mine = (t < NBLK) ? g_bsum[t] : 0;
    s[t] = mine;
    __syncthreads();
#pragma unroll
    for (int o = 1; o < 128; o <<= 1) {
        int v = (t >= o) ? s[t - o] : 0;
        __syncthreads();
        s[t] += v;
        __syncthreads();
    }
    g_bsum[t] = s[t] - mine;
}

// ---------------------------------------------------------------------------
// Atomic-free CSR fill: 4 edges/thread, int4 loads.
// ---------------------------------------------------------------------------
__global__ void fill_csr(const int* __restrict__ esrc,
                         const int* __restrict__ edst) {
    int gi = blockIdx.x * blockDim.x + threadIdx.x;
    if (gi >= E4) return;
    int4 d4 = ((const int4*)edst)[gi];
    int4 s4 = ((const int4*)esrc)[gi];
    int4 r4 = ((const int4*)g_rank)[gi];
    g_csr[g_rowstart[d4.x] + g_bsum[d4.x >> 10] + r4.x] = s4.x;
    g_csr[g_rowstart[d4.y] + g_bsum[d4.y >> 10] + r4.y] = s4.y;
    g_csr[g_rowstart[d4.z] + g_bsum[d4.z >> 10] + r4.z] = s4.z;
    g_csr[g_rowstart[d4.w] + g_bsum[d4.w >> 10] + r4.w] = s4.w;
}

// ---------------------------------------------------------------------------
// Segmented gather-mean, fp16 depth-2 tree + broadcast int4 CSR reads.
// One warp per dst node; fp32 accumulation across groups; exact head/tail.
// ---------------------------------------------------------------------------
__global__ void __launch_bounds__(256)
gather_mean16() {
    int gtid = blockIdx.x * blockDim.x + threadIdx.x;
    int v    = gtid >> 5;
    int lane = threadIdx.x & 31;
    if (v >= N_NODES) return;

    int deg = g_deg[v];
    int rs  = g_rowstart[v] + g_bsum[v >> 10];
    int re  = rs + deg;

    const __half2* hb = g_h16 + lane * 2;   // lane's 2 half2 columns

    float2 f01 = make_float2(0.f, 0.f);
    float2 f23 = make_float2(0.f, 0.f);

    int i = rs;
    // head: advance to 16B-aligned csr index
    int head = (4 - (rs & 3)) & 3;
    if (head > deg) head = deg;
    for (int k = 0; k < head; k++, i++) {
        int s0 = g_csr[i];
        uint2 u0 = *(const uint2*)(hb + (size_t)s0 * 64);
        float2 fx = __half22float2(*reinterpret_cast<__half2*>(&u0.x));
        float2 fy = __half22float2(*reinterpret_cast<__half2*>(&u0.y));
        f01.x += fx.x; f01.y += fx.y;
        f23.x += fy.x; f23.y += fy.y;
    }
    // main: one LDG.128 broadcast per 4 edges
    for (; i + 3 < re; i += 4) {
        int4 s4 = *(const int4*)(g_csr + i);
        uint2 u0 = *(const uint2*)(hb + (size_t)s4.x * 64);
        uint2 u1 = *(const uint2*)(hb + (size_t)s4.y * 64);
        uint2 u2 = *(const uint2*)(hb + (size_t)s4.z * 64);
        uint2 u3 = *(const uint2*)(hb + (size_t)s4.w * 64);
        __half2 ax = __hadd2(
            __hadd2(*reinterpret_cast<__half2*>(&u0.x), *reinterpret_cast<__half2*>(&u1.x)),
            __hadd2(*reinterpret_cast<__half2*>(&u2.x), *reinterpret_cast<__half2*>(&u3.x)));
        __half2 ay = __hadd2(
            __hadd2(*reinterpret_cast<__half2*>(&u0.y), *reinterpret_cast<__half2*>(&u1.y)),
            __hadd2(*reinterpret_cast<__half2*>(&u2.y), *reinterpret_cast<__half2*>(&u3.y)));
        float2 fx = __half22float2(ax);
        float2 fy = __half22float2(ay);
        f01.x += fx.x; f01.y += fx.y;
        f23.x += fy.x; f23.y += fy.y;
    }
    // tail
    for (; i < re; i++) {
        int s0 = g_csr[i];
        uint2 u0 = *(const uint2*)(hb + (size_t)s0 * 64);
        float2 fx = __half22float2(*reinterpret_cast<__half2*>(&u0.x));
        float2 fy = __half22float2(*reinterpret_cast<__half2*>(&u0.y));
        f01.x += fx.x; f01.y += fx.y;
        f23.x += fy.x; f23.y += fy.y;
    }

    float inv = 1.0f / (float)max(deg, 1);
    __half2 p0 = __floats2half2_rn(f01.x * inv, f01.y * inv);
    __half2 p1 = __floats2half2_rn(f23.x * inv, f23.y * inv);
    uint2 u;
    u.x = *reinterpret_cast<uint32_t*>(&p0);
    u.y = *reinterpret_cast<uint32_t*>(&p1);
    *(uint2*)(g_c16 + (size_t)v * 64 + lane * 2) = u;
}

// ---------------------------------------------------------------------------
// fp16 GEMM, single-term A and W (exact R11 version — no cp.async).
// Block: 256 thr (8 warps), tile M=128 N=128, 4 K-chunks of 64. 2 blocks/SM.
// ---------------------------------------------------------------------------
#define SMW     0         // 4 chunks x 16KB = 65536 (reused for output stage)
#define SMA     65536     // 16KB
#define SM_BIAS 81920
#define SM_SSQ  82432
#define SM_TOTAL 83456

__global__ void __launch_bounds__(256, 2)
gemm_mma(const float* __restrict__ bias, float* __restrict__ out) {
    extern __shared__ char sm[];
    const uint32_t sb = smem_u32(sm);
    const int tid  = threadIdx.x;
    const int wid  = tid >> 5;
    const int lane = tid & 31;
    const int m0   = blockIdx.x * 128;
    const int mwarp = (wid >> 1) * 32;
    const int nwarp = (wid & 1) * 64;

    if (tid < 128) *(float*)(sm + SM_BIAS + tid * 4) = bias[tid];

    // ---- preload W fp16 (4 chunks, SW128) ----
    {
        int r = tid >> 1, half = tid & 1;
#pragma unroll
        for (int c = 0; c < 4; c++) {
#pragma unroll
            for (int j = 0; j < 4; j++) {
                uint32_t sw = SW128((uint32_t)(r * 128 + half * 64 + j * 16));
                *(uint4*)(sm + SMW + c * 16384 + sw) =
                    *(const uint4*)(g_Wf + r * K2 + c * 64 + half * 32 + j * 8);
            }
        }
    }

    const int r = tid >> 1, half = tid & 1;
    int mg = m0 + r;
    if (mg >= N_NODES) mg = N_NODES - 1;

    float acc[2][8][4];
#pragma unroll
    for (int mt = 0; mt < 2; mt++)
#pragma unroll
        for (int nt = 0; nt < 8; nt++)
#pragma unroll
            for (int q = 0; q < 4; q++) acc[mt][nt][q] = 0.0f;

    for (int ch = 0; ch < 4; ch++) {
        // ---- A chunk: fp16 direct copy, SW128 ----
        const __half2* asrc = ((ch < 2) ? g_h16 : g_c16) +
                              (size_t)mg * 64 + (ch & 1) * 32 + half * 16;
#pragma unroll
        for (int j = 0; j < 4; j++) {
            uint4 v = *(const uint4*)(asrc + j * 4);
            uint32_t sw = SW128((uint32_t)(r * 128 + half * 64 + j * 16));
            *(uint4*)(sm + SMA + sw) = v;
        }
        __syncthreads();

#pragma unroll
        for (int ks = 0; ks < 4; ks++) {
            const uint32_t kc2 = ks * 32;

            uint32_t af[2][4];
#pragma unroll
            for (int mt = 0; mt < 2; mt++) {
                uint32_t rowoff = mwarp + mt * 16 + (lane & 7) + ((lane >> 3) & 1) * 8;
                uint32_t colb   = kc2 + ((lane >> 4) << 4);
                uint32_t sw = SW128(rowoff * 128 + colb);
                ldsm_x4(af[mt], sb + SMA + sw);
            }
            uint32_t bw[4][4];
#pragma unroll
            for (int tp = 0; tp < 4; tp++) {
                uint32_t j = lane >> 3;
                uint32_t row = nwarp + tp * 16 + (lane & 7) + ((j >> 1) << 3);
                uint32_t colb = kc2 + ((j & 1) << 4);
                uint32_t sw = SW128(row * 128 + colb);
                ldsm_x4(bw[tp], sb + SMW + ch * 16384 + sw);
            }
#pragma unroll
            for (int mt = 0; mt < 2; mt++) {
#pragma unroll
                for (int nt = 0; nt < 8; nt++) {
                    uint32_t b0 = bw[nt >> 1][(nt & 1) * 2 + 0];
                    uint32_t b1 = bw[nt >> 1][(nt & 1) * 2 + 1];
                    mma_f16(acc[mt][nt], af[mt], b0, b1);
                }
            }
        }
        __syncthreads();
    }

    // ---- epilogue: bias -> ssq -> normalize -> relu -> staged store ----
#pragma unroll
    for (int mt = 0; mt < 2; mt++)
#pragma unroll
        for (int nt = 0; nt < 8; nt++) {
            float2 bb = *(const float2*)(sm + SM_BIAS +
                                         (nwarp + nt * 8 + (lane & 3) * 2) * 4);
            acc[mt][nt][0] += bb.x;
            acc[mt][nt][1] += bb.y;
            acc[mt][nt][2] += bb.x;
            acc[mt][nt][3] += bb.y;
        }

    float pp[2][2] = {{0.f, 0.f}, {0.f, 0.f}};
#pragma unroll
    for (int mt = 0; mt < 2; mt++)
#pragma unroll
        for (int nt = 0; nt < 8; nt++) {
            pp[mt][0] += acc[mt][nt][0] * acc[mt][nt][0] +
                         acc[mt][nt][1] * acc[mt][nt][1];
            pp[mt][1] += acc[mt][nt][2] * acc[mt][nt][2] +
                         acc[mt][nt][3] * acc[mt][nt][3];
        }
#pragma unroll
    for (int off = 1; off <= 2; off <<= 1) {
#pragma unroll
        for (int mt = 0; mt < 2; mt++) {
            pp[mt][0] += __shfl_xor_sync(~0u, pp[mt][0], off);
            pp[mt][1] += __shfl_xor_sync(~0u, pp[mt][1], off);
        }
    }
    if ((lane & 3) == 0) {
#pragma unroll
        for (int mt = 0; mt < 2; mt++)
#pragma unroll
            for (int hh = 0; hh < 2; hh++) {
                int row = mwarp + mt * 16 + (lane >> 2) + hh * 8;
                *(float*)(sm + SM_SSQ + (wid & 1) * 512 + row * 4) = pp[mt][hh];
            }
    }
    __syncthreads();

    float sc[2][2];
#pragma unroll
    for (int mt = 0; mt < 2; mt++)
#pragma unroll
        for (int hh = 0; hh < 2; hh++) {
            int row = mwarp + mt * 16 + (lane >> 2) + hh * 8;
            float s = *(const float*)(sm + SM_SSQ + row * 4) +
                      *(const float*)(sm + SM_SSQ + 512 + row * 4);
            sc[mt][hh] = 1.0f / fmaxf(sqrtf(s), 1e-12f);
        }
    __syncthreads();

    // stage relu'd rows into SMEM (reuse W region) then coalesced store
#pragma unroll
    for (int mt = 0; mt < 2; mt++) {
#pragma unroll
        for (int nt = 0; nt < 8; nt++) {
            int coln = nwarp + nt * 8 + (lane & 3) * 2;
            int row0 = mwarp + mt * 16 + (lane >> 2);
            int row1 = row0 + 8;
            float2 v0, v1;
            v0.x = fmaxf(acc[mt][nt][0] * sc[mt][0], 0.0f);
            v0.y = fmaxf(acc[mt][nt][1] * sc[mt][0], 0.0f);
            v1.x = fmaxf(acc[mt][nt][2] * sc[mt][1], 0.0f);
            v1.y = fmaxf(acc[mt][nt][3] * sc[mt][1], 0.0f);
            *(float2*)(sm + row0 * 512 + ((coln * 4) ^ ((row0 & 7) << 4))) = v0;
            *(float2*)(sm + row1 * 512 + ((coln * 4) ^ ((row1 & 7) << 4))) = v1;
        }
    }
    __syncthreads();

#pragma unroll
    for (int i = 0; i < 16; i++) {
        int idx = tid + i * 256;
        int rr = idx >> 5;
        int p  = idx & 31;
        int mgl = m0 + rr;
        if (mgl < N_NODES) {
            float4 o = *(const float4*)(sm + rr * 512 + ((p * 16) ^ ((rr & 7) << 4)));
            *(float4*)(out + (size_t)mgl * D + p * 4) = o;
        }
    }
}

// ---------------------------------------------------------------------------
extern "C" void kernel_launch(void* const* d_in, const int* in_sizes, int n_in,
                              void* d_out, int out_size) {
    const float* h    = (const float*)d_in[0];
    const float* W    = (const float*)d_in[1];
    const float* bias = (const float*)d_in[2];
    const int*   esrc = (const int*)d_in[3];
    const int*   edst = (const int*)d_in[4];
    float*       out  = (float*)d_out;

    void* p_deg = nullptr;
    cudaGetSymbolAddress(&p_deg, g_deg);
    cudaMemsetAsync(p_deg, 0, sizeof(int) * N_NODES, 0);

    cudaFuncSetAttribute(gemm_mma, cudaFuncAttributeMaxDynamicSharedMemorySize,
                         SM_TOTAL);

    prep_hist<<<1728 + (E4 + 255) / 256, 256>>>(W, h, edst);
    scan_blocks<<<NBLK, 1024>>>();
    scan_top<<<1, 128>>>();
    fill_csr<<<(E4 + 255) / 256, 256>>>(esrc, edst);
    gather_mean16<<<(N_NODES * 32 + 255) / 256, 256>>>();
    gemm_mma<<<(N_NODES + 127) / 128, 256, SM_TOTAL>>>(bias, out);
}

// round 14
// speedup vs baseline: 1.0438x; 1.0438x over previous
#include <cuda_runtime.h>
#include <cuda_bf16.h>
#include <cuda_fp16.h>
#include <cstdint>

#define N_NODES 100000
#define N_EDGES 1600000
#define D 128
#define K2 256   // 2*D
#define NBLK 98  // ceil(N_NODES / 1024)
#define E4 (N_EDGES / 4)   // 400000

// Scratch (no device mallocs allowed)
__device__ __half2 g_h16[(size_t)N_NODES * (D / 2)];  // fp16 h (25.6 MB)
__device__ __half2 g_c16[(size_t)N_NODES * (D / 2)];  // fp16 c (25.6 MB)
__device__ int   g_deg[N_NODES];
__device__ int   g_rank[N_EDGES];
__device__ int   g_rowstart[N_NODES];
__device__ int   g_bsum[128];
__device__ int   g_csr[N_EDGES];
__device__ __half g_Wf[D * K2];                // W fp16 [n][k], full K

// ===========================================================================
// Helpers
// ===========================================================================
__device__ __forceinline__ uint32_t smem_u32(const void* p) {
    uint32_t a;
    asm("{ .reg .u64 t; cvta.to.shared.u64 t, %1; cvt.u32.u64 %0, t; }"
        : "=r"(a) : "l"(p));
    return a;
}
#define SW128(o) ((o) ^ (((o) >> 3) & 0x70))

__device__ __forceinline__ void ldsm_x4(uint32_t* r, uint32_t addr) {
    asm volatile("ldmatrix.sync.aligned.m8n8.x4.shared.b16 {%0,%1,%2,%3}, [%4];"
                 : "=r"(r[0]), "=r"(r[1]), "=r"(r[2]), "=r"(r[3]) : "r"(addr));
}
__device__ __forceinline__ void mma_f16(float* c, const uint32_t* a,
                                        uint32_t b0, uint32_t b1) {
    asm volatile(
        "mma.sync.aligned.m16n8k16.row.col.f32.f16.f16.f32 "
        "{%0,%1,%2,%3}, {%4,%5,%6,%7}, {%8,%9}, {%0,%1,%2,%3};"
        : "+f"(c[0]), "+f"(c[1]), "+f"(c[2]), "+f"(c[3])
        : "r"(a[0]), "r"(a[1]), "r"(a[2]), "r"(a[3]), "r"(b0), "r"(b1));
}
__device__ __forceinline__ __half2 h2(uint32_t u) {
    return *reinterpret_cast<__half2*>(&u);
}

// ---------------------------------------------------------------------------
// Fused prep + histogram. Block ranges:
//   [0,128)      : W -> fp16
//   [128,1728)   : h -> fp16
//   [1728,3291)  : edge histogram (4 edges/thread, int4) + rank record
// ---------------------------------------------------------------------------
__global__ void prep_hist(const float* __restrict__ W,
                          const float* __restrict__ h,
                          const int* __restrict__ edst) {
    int b = blockIdx.x;
    int t = threadIdx.x;
    if (b < 128) {
        int i = b * 256 + t;                       // 0..32767
        g_Wf[i] = __float2half(W[i]);
    } else if (b < 1728) {
        int i = (b - 128) * 256 + t;               // float4 index
        int stride = 1600 * 256;
        const int total = N_NODES * (D / 4);       // 3.2M
        for (; i < total; i += stride) {
            float4 v = *(const float4*)(h + (size_t)i * 4);
            __half2 a = __floats2half2_rn(v.x, v.y);
            __half2 c = __floats2half2_rn(v.z, v.w);
            uint2 u;
            u.x = *reinterpret_cast<uint32_t*>(&a);
            u.y = *reinterpret_cast<uint32_t*>(&c);
            *(uint2*)(g_h16 + (size_t)i * 2) = u;
        }
    } else {
        int gi = (b - 1728) * 256 + t;             // int4 edge-group index
        if (gi < E4) {
            int4 d4 = ((const int4*)edst)[gi];
            int4 r4;
            r4.x = atomicAdd(&g_deg[d4.x], 1);
            r4.y = atomicAdd(&g_deg[d4.y], 1);
            r4.z = atomicAdd(&g_deg[d4.z], 1);
            r4.w = atomicAdd(&g_deg[d4.w], 1);
            ((int4*)g_rank)[gi] = r4;
        }
    }
}

// ---------------------------------------------------------------------------
// Scans
// ---------------------------------------------------------------------------
__global__ void scan_blocks() {
    __shared__ int wsum[32];
    int t = threadIdx.x, b = blockIdx.x;
    int i = b * 1024 + t;
    int v = (i < N_NODES) ? g_deg[i] : 0;
    int x = v;
#pragma unroll
    for (int o = 1; o < 32; o <<= 1) {
        int y = __shfl_up_sync(~0u, x, o);
        if ((t & 31) >= o) x += y;
    }
    if ((t & 31) == 31) wsum[t >> 5] = x;
    __syncthreads();
    if (t < 32) {
        int s = wsum[t];
#pragma unroll
        for (int o = 1; o < 32; o <<= 1) {
            int y = __shfl_up_sync(~0u, s, o);
            if (t >= o) s += y;
        }
        wsum[t] = s;
    }
    __syncthreads();
    int off = (t >= 32) ? wsum[(t >> 5) - 1] : 0;
    int incl = x + off;
    if (i < N_NODES) g_rowstart[i] = incl - v;
    if (t == 1023) g_bsum[b] = incl;
}

__global__ void scan_top() {
    __shared__ int s[128];
    int t = threadIdx.x;
    int mine = (t < NBLK) ? g_bsum[t] : 0;
    s[t] = mine;
    __syncthreads();
#pragma unroll
    for (int o = 1; o < 128; o <<= 1) {
        int v = (t >= o) ? s[t - o] : 0;
        __syncthreads();
        s[t] += v;
        __syncthreads();
    }
    g_bsum[t] = s[t] - mine;
}

// ---------------------------------------------------------------------------
// Atomic-free CSR fill: 4 edges/thread, int4 loads.
// ---------------------------------------------------------------------------
__global__ void fill_csr(const int* __restrict__ esrc,
                         const int* __restrict__ edst) {
    int gi = blockIdx.x * blockDim.x + threadIdx.x;
    if (gi >= E4) return;
    int4 d4 = ((const int4*)edst)[gi];
    int4 s4 = ((const int4*)esrc)[gi];
    int4 r4 = ((const int4*)g_rank)[gi];
    g_csr[g_rowstart[d4.x] + g_bsum[d4.x >> 10] + r4.x] = s4.x;
    g_csr[g_rowstart[d4.y] + g_bsum[d4.y >> 10] + r4.y] = s4.y;
    g_csr[g_rowstart[d4.z] + g_bsum[d4.z >> 10] + r4.z] = s4.z;
    g_csr[g_rowstart[d4.w] + g_bsum[d4.w >> 10] + r4.w] = s4.w;
}

// ---------------------------------------------------------------------------
// Segmented gather-mean, half-warp variant: 2 nodes per warp.
// Lanes 0-15 -> node 2w, lanes 16-31 -> node 2w+1. Each lane owns 16B of the
// row (uint4 = 4 half2 = 8 cols). fp16 depth-2 tree over 4 edges, fp32
// accumulation across groups; scalar index loads (independent, MLP=4).
// ---------------------------------------------------------------------------
__global__ void __launch_bounds__(256)
gather_mean16() {
    int gtid = blockIdx.x * blockDim.x + threadIdx.x;
    int w    = gtid >> 5;
    int lane = threadIdx.x & 31;
    int sub  = lane >> 4;                 // which node of the pair
    int sl   = lane & 15;                 // 16B slot within row
    int v    = w * 2 + sub;
    if (v >= N_NODES) return;

    int deg = g_deg[v];
    int rs  = g_rowstart[v] + g_bsum[v >> 10];
    int re  = rs + deg;

    const __half2* hb = g_h16 + sl * 4;   // lane's 4 half2 columns

    float2 f0 = make_float2(0.f, 0.f);
    float2 f1 = make_float2(0.f, 0.f);
    float2 f2 = make_float2(0.f, 0.f);
    float2 f3 = make_float2(0.f, 0.f);

    int i = rs;
    for (; i + 3 < re; i += 4) {
        int s0 = g_csr[i], s1 = g_csr[i + 1], s2 = g_csr[i + 2], s3 = g_csr[i + 3];
        uint4 u0 = *(const uint4*)(hb + (size_t)s0 * 64);
        uint4 u1 = *(const uint4*)(hb + (size_t)s1 * 64);
        uint4 u2 = *(const uint4*)(hb + (size_t)s2 * 64);
        uint4 u3 = *(const uint4*)(hb + (size_t)s3 * 64);
        __half2 c0 = __hadd2(__hadd2(h2(u0.x), h2(u1.x)), __hadd2(h2(u2.x), h2(u3.x)));
        __half2 c1 = __hadd2(__hadd2(h2(u0.y), h2(u1.y)), __hadd2(h2(u2.y), h2(u3.y)));
        __half2 c2 = __hadd2(__hadd2(h2(u0.z), h2(u1.z)), __hadd2(h2(u2.z), h2(u3.z)));
        __half2 c3 = __hadd2(__hadd2(h2(u0.w), h2(u1.w)), __hadd2(h2(u2.w), h2(u3.w)));
        float2 g0 = __half22float2(c0);
        float2 g1 = __half22float2(c1);
        float2 g2 = __half22float2(c2);
        float2 g3 = __half22float2(c3);
        f0.x += g0.x; f0.y += g0.y;
        f1.x += g1.x; f1.y += g1.y;
        f2.x += g2.x; f2.y += g2.y;
        f3.x += g3.x; f3.y += g3.y;
    }
    for (; i < re; i++) {
        int s0 = g_csr[i];
        uint4 u0 = *(const uint4*)(hb + (size_t)s0 * 64);
        float2 g0 = __half22float2(h2(u0.x));
        float2 g1 = __half22float2(h2(u0.y));
        float2 g2 = __half22float2(h2(u0.z));
        float2 g3 = __half22float2(h2(u0.w));
        f0.x += g0.x; f0.y += g0.y;
        f1.x += g1.x; f1.y += g1.y;
        f2.x += g2.x; f2.y += g2.y;
        f3.x += g3.x; f3.y += g3.y;
    }

    float inv = 1.0f / (float)max(deg, 1);
    __half2 p0 = __floats2half2_rn(f0.x * inv, f0.y * inv);
    __half2 p1 = __floats2half2_rn(f1.x * inv, f1.y * inv);
    __half2 p2 = __floats2half2_rn(f2.x * inv, f2.y * inv);
    __half2 p3 = __floats2half2_rn(f3.x * inv, f3.y * inv);
    uint4 u;
    u.x = *reinterpret_cast<uint32_t*>(&p0);
    u.y = *reinterpret_cast<uint32_t*>(&p1);
    u.z = *reinterpret_cast<uint32_t*>(&p2);
    u.w = *reinterpret_cast<uint32_t*>(&p3);
    *(uint4*)(g_c16 + (size_t)v * 64 + sl * 4) = u;
}

// ---------------------------------------------------------------------------
// fp16 GEMM, single-term A and W (exact R11 version — no cp.async).
// Block: 256 thr (8 warps), tile M=128 N=128, 4 K-chunks of 64. 2 blocks/SM.
// ---------------------------------------------------------------------------
#define SMW     0         // 4 chunks x 16KB = 65536 (reused for output stage)
#define SMA     65536     // 16KB
#define SM_BIAS 81920
#define SM_SSQ  82432
#define SM_TOTAL 83456

__global__ void __launch_bounds__(256, 2)
gemm_mma(const float* __restrict__ bias, float* __restrict__ out) {
    extern __shared__ char sm[];
    const uint32_t sb = smem_u32(sm);
    const int tid  = threadIdx.x;
    const int wid  = tid >> 5;
    const int lane = tid & 31;
    const int m0   = blockIdx.x * 128;
    const int mwarp = (wid >> 1) * 32;
    const int nwarp = (wid & 1) * 64;

    if (tid < 128) *(float*)(sm + SM_BIAS + tid * 4) = bias[tid];

    // ---- preload W fp16 (4 chunks, SW128) ----
    {
        int r = tid >> 1, half = tid & 1;
#pragma unroll
        for (int c = 0; c < 4; c++) {
#pragma unroll
            for (int j = 0; j < 4; j++) {
                uint32_t sw = SW128((uint32_t)(r * 128 + half * 64 + j * 16));
                *(uint4*)(sm + SMW + c * 16384 + sw) =
                    *(const uint4*)(g_Wf + r * K2 + c * 64 + half * 32 + j * 8);
            }
        }
    }

    const int r = tid >> 1, half = tid & 1;
    int mg = m0 + r;
    if (mg >= N_NODES) mg = N_NODES - 1;

    float acc[2][8][4];
#pragma unroll
    for (int mt = 0; mt < 2; mt++)
#pragma unroll
        for (int nt = 0; nt < 8; nt++)
#pragma unroll
            for (int q = 0; q < 4; q++) acc[mt][nt][q] = 0.0f;

    for (int ch = 0; ch < 4; ch++) {
        // ---- A chunk: fp16 direct copy, SW128 ----
        const __half2* asrc = ((ch < 2) ? g_h16 : g_c16) +
                              (size_t)mg * 64 + (ch & 1) * 32 + half * 16;
#pragma unroll
        for (int j = 0; j < 4; j++) {
            uint4 v = *(const uint4*)(asrc + j * 4);
            uint32_t sw = SW128((uint32_t)(r * 128 + half * 64 + j * 16));
            *(uint4*)(sm + SMA + sw) = v;
        }
        __syncthreads();

#pragma unroll
        for (int ks = 0; ks < 4; ks++) {
            const uint32_t kc2 = ks * 32;

            uint32_t af[2][4];
#pragma unroll
            for (int mt = 0; mt < 2; mt++) {
                uint32_t rowoff = mwarp + mt * 16 + (lane & 7) + ((lane >> 3) & 1) * 8;
                uint32_t colb   = kc2 + ((lane >> 4) << 4);
                uint32_t sw = SW128(rowoff * 128 + colb);
                ldsm_x4(af[mt], sb + SMA + sw);
            }
            uint32_t bw[4][4];
#pragma unroll
            for (int tp = 0; tp < 4; tp++) {
                uint32_t j = lane >> 3;
                uint32_t row = nwarp + tp * 16 + (lane & 7) + ((j >> 1) << 3);
                uint32_t colb = kc2 + ((j & 1) << 4);
                uint32_t sw = SW128(row * 128 + colb);
                ldsm_x4(bw[tp], sb + SMW + ch * 16384 + sw);
            }
#pragma unroll
            for (int mt = 0; mt < 2; mt++) {
#pragma unroll
                for (int nt = 0; nt < 8; nt++) {
                    uint32_t b0 = bw[nt >> 1][(nt & 1) * 2 + 0];
                    uint32_t b1 = bw[nt >> 1][(nt & 1) * 2 + 1];
                    mma_f16(acc[mt][nt], af[mt], b0, b1);
                }
            }
        }
        __syncthreads();
    }

    // ---- epilogue: bias -> ssq -> normalize -> relu -> staged store ----
#pragma unroll
    for (int mt = 0; mt < 2; mt++)
#pragma unroll
        for (int nt = 0; nt < 8; nt++) {
            float2 bb = *(const float2*)(sm + SM_BIAS +
                                         (nwarp + nt * 8 + (lane & 3) * 2) * 4);
            acc[mt][nt][0] += bb.x;
            acc[mt][nt][1] += bb.y;
            acc[mt][nt][2] += bb.x;
            acc[mt][nt][3] += bb.y;
        }

    float pp[2][2] = {{0.f, 0.f}, {0.f, 0.f}};
#pragma unroll
    for (int mt = 0; mt < 2; mt++)
#pragma unroll
        for (int nt = 0; nt < 8; nt++) {
            pp[mt][0] += acc[mt][nt][0] * acc[mt][nt][0] +
                         acc[mt][nt][1] * acc[mt][nt][1];
            pp[mt][1] += acc[mt][nt][2] * acc[mt][nt][2] +
                         acc[mt][nt][3] * acc[mt][nt][3];
        }
#pragma unroll
    for (int off = 1; off <= 2; off <<= 1) {
#pragma unroll
        for (int mt = 0; mt < 2; mt++) {
            pp[mt][0] += __shfl_xor_sync(~0u, pp[mt][0], off);
            pp[mt][1] += __shfl_xor_sync(~0u, pp[mt][1], off);
        }
    }
    if ((lane & 3) == 0) {
#pragma unroll
        for (int mt = 0; mt < 2; mt++)
#pragma unroll
            for (int hh = 0; hh < 2; hh++) {
                int row = mwarp + mt * 16 + (lane >> 2) + hh * 8;
                *(float*)(sm + SM_SSQ + (wid & 1) * 512 + row * 4) = pp[mt][hh];
            }
    }
    __syncthreads();

    float sc[2][2];
#pragma unroll
    for (int mt = 0; mt < 2; mt++)
#pragma unroll
        for (int hh = 0; hh < 2; hh++) {
            int row = mwarp + mt * 16 + (lane >> 2) + hh * 8;
            float s = *(const float*)(sm + SM_SSQ + row * 4) +
                      *(const float*)(sm + SM_SSQ + 512 + row * 4);
            sc[mt][hh] = 1.0f / fmaxf(sqrtf(s), 1e-12f);
        }
    __syncthreads();

    // stage relu'd rows into SMEM (reuse W region) then coalesced store
#pragma unroll
    for (int mt = 0; mt < 2; mt++) {
#pragma unroll
        for (int nt = 0; nt < 8; nt++) {
            int coln = nwarp + nt * 8 + (lane & 3) * 2;
            int row0 = mwarp + mt * 16 + (lane >> 2);
            int row1 = row0 + 8;
            float2 v0, v1;
            v0.x = fmaxf(acc[mt][nt][0] * sc[mt][0], 0.0f);
            v0.y = fmaxf(acc[mt][nt][1] * sc[mt][0], 0.0f);
            v1.x = fmaxf(acc[mt][nt][2] * sc[mt][1], 0.0f);
            v1.y = fmaxf(acc[mt][nt][3] * sc[mt][1], 0.0f);
            *(float2*)(sm + row0 * 512 + ((coln * 4) ^ ((row0 & 7) << 4))) = v0;
            *(float2*)(sm + row1 * 512 + ((coln * 4) ^ ((row1 & 7) << 4))) = v1;
        }
    }
    __syncthreads();

#pragma unroll
    for (int i = 0; i < 16; i++) {
        int idx = tid + i * 256;
        int rr = idx >> 5;
        int p  = idx & 31;
        int mgl = m0 + rr;
        if (mgl < N_NODES) {
            float4 o = *(const float4*)(sm + rr * 512 + ((p * 16) ^ ((rr & 7) << 4)));
            *(float4*)(out + (size_t)mgl * D + p * 4) = o;
        }
    }
}

// ---------------------------------------------------------------------------
extern "C" void kernel_launch(void* const* d_in, const int* in_sizes, int n_in,
                              void* d_out, int out_size) {
    const float* h    = (const float*)d_in[0];
    const float* W    = (const float*)d_in[1];
    const float* bias = (const float*)d_in[2];
    const int*   esrc = (const int*)d_in[3];
    const int*   edst = (const int*)d_in[4];
    float*       out  = (float*)d_out;

    void* p_deg = nullptr;
    cudaGetSymbolAddress(&p_deg, g_deg);
    cudaMemsetAsync(p_deg, 0, sizeof(int) * N_NODES, 0);

    cudaFuncSetAttribute(gemm_mma, cudaFuncAttributeMaxDynamicSharedMemorySize,
                         SM_TOTAL);

    prep_hist<<<1728 + (E4 + 255) / 256, 256>>>(W, h, edst);
    scan_blocks<<<NBLK, 1024>>>();
    scan_top<<<1, 128>>>();
    fill_csr<<<(E4 + 255) / 256, 256>>>(esrc, edst);
    // 2 nodes per warp -> 50000 warps -> 6250 blocks of 256
    gather_mean16<<<(N_NODES / 2 * 32 + 255) / 256, 256>>>();
    gemm_mma<<<(N_NODES + 127) / 128, 256, SM_TOTAL>>>(bias, out);
}

// round 15
// speedup vs baseline: 1.0930x; 1.0471x over previous
#include <cuda_runtime.h>
#include <cuda_bf16.h>
#include <cuda_fp16.h>
#include <cstdint>

#define N_NODES 100000
#define N_EDGES 1600000
#define D 128
#define K2 256   // 2*D
#define NBLK 98  // ceil(N_NODES / 1024)
#define E4 (N_EDGES / 4)   // 400000

// Scratch (no device mallocs allowed)
__device__ __half2 g_h16[(size_t)N_NODES * (D / 2)];  // fp16 h (25.6 MB)
__device__ __half2 g_c16[(size_t)N_NODES * (D / 2)];  // fp16 c (25.6 MB)
__device__ int   g_deg[N_NODES];
__device__ int   g_rank[N_EDGES];
__device__ int   g_rowstart[N_NODES];
__device__ int   g_bsum[128];
__device__ int   g_csr[N_EDGES];
__device__ __half g_Wf[D * K2];                // W fp16 [n][k], full K

// ===========================================================================
// Helpers
// ===========================================================================
__device__ __forceinline__ uint32_t smem_u32(const void* p) {
    uint32_t a;
    asm("{ .reg .u64 t; cvta.to.shared.u64 t, %1; cvt.u32.u64 %0, t; }"
        : "=r"(a) : "l"(p));
    return a;
}
#define SW128(o) ((o) ^ (((o) >> 3) & 0x70))

__device__ __forceinline__ void ldsm_x4(uint32_t* r, uint32_t addr) {
    asm volatile("ldmatrix.sync.aligned.m8n8.x4.shared.b16 {%0,%1,%2,%3}, [%4];"
                 : "=r"(r[0]), "=r"(r[1]), "=r"(r[2]), "=r"(r[3]) : "r"(addr));
}
__device__ __forceinline__ void mma_f16(float* c, const uint32_t* a,
                                        uint32_t b0, uint32_t b1) {
    asm volatile(
        "mma.sync.aligned.m16n8k16.row.col.f32.f16.f16.f32 "
        "{%0,%1,%2,%3}, {%4,%5,%6,%7}, {%8,%9}, {%0,%1,%2,%3};"
        : "+f"(c[0]), "+f"(c[1]), "+f"(c[2]), "+f"(c[3])
        : "r"(a[0]), "r"(a[1]), "r"(a[2]), "r"(a[3]), "r"(b0), "r"(b1));
}

// ---------------------------------------------------------------------------
// Fused prep + histogram, parity-interleaved so the DRAM-streaming converts
// and the atomic-bound histogram co-run in every wave.
//   even blocks: k=b/2  -> hist(k) if k<1563 else h-cvt(1517 + k-1563)
//   odd  blocks: k=b/2  -> W-cvt(k) if k<128 else h-cvt(k-128)
// Totals: hist 1563, W 128, h-cvt 1600 (83 from even overflow + 1517 odd).
// ---------------------------------------------------------------------------
__global__ void prep_hist(const float* __restrict__ W,
                          const float* __restrict__ h,
                          const int* __restrict__ edst) {
    int b = blockIdx.x;
    int t = threadIdx.x;
    int k = b >> 1;
    int hcvt_id = -1;

    if ((b & 1) == 0) {
        if (k < 1563) {
            // ---- histogram: 4 edges/thread via int4 + rank record ----
            int gi = k * 256 + t;
            if (gi < E4) {
                int4 d4 = ((const int4*)edst)[gi];
                int4 r4;
                r4.x = atomicAdd(&g_deg[d4.x], 1);
                r4.y = atomicAdd(&g_deg[d4.y], 1);
                r4.z = atomicAdd(&g_deg[d4.z], 1);
                r4.w = atomicAdd(&g_deg[d4.w], 1);
                ((int4*)g_rank)[gi] = r4;
            }
            return;
        }
        hcvt_id = 1517 + (k - 1563);               // 1517..1599
    } else {
        if (k < 128) {
            // ---- W -> fp16 ----
            int i = k * 256 + t;                   // 0..32767
            g_Wf[i] = __float2half(W[i]);
            return;
        }
        hcvt_id = k - 128;                         // 0..1516
    }

    // ---- h -> fp16 (grid-stride over 1600 logical blocks) ----
    int i = hcvt_id * 256 + t;                     // float4 index
    const int stride = 1600 * 256;
    const int total = N_NODES * (D / 4);           // 3.2M
    for (; i < total; i += stride) {
        float4 v = *(const float4*)(h + (size_t)i * 4);
        __half2 a = __floats2half2_rn(v.x, v.y);
        __half2 c = __floats2half2_rn(v.z, v.w);
        uint2 u;
        u.x = *reinterpret_cast<uint32_t*>(&a);
        u.y = *reinterpret_cast<uint32_t*>(&c);
        *(uint2*)(g_h16 + (size_t)i * 2) = u;
    }
}

// ---------------------------------------------------------------------------
// Scans
// ---------------------------------------------------------------------------
__global__ void scan_blocks() {
    __shared__ int wsum[32];
    int t = threadIdx.x, b = blockIdx.x;
    int i = b * 1024 + t;
    int v = (i < N_NODES) ? g_deg[i] : 0;
    int x = v;
#pragma unroll
    for (int o = 1; o < 32; o <<= 1) {
        int y = __shfl_up_sync(~0u, x, o);
        if ((t & 31) >= o) x += y;
    }
    if ((t & 31) == 31) wsum[t >> 5] = x;
    __syncthreads();
    if (t < 32) {
        int s = wsum[t];
#pragma unroll
        for (int o = 1; o < 32; o <<= 1) {
            int y = __shfl_up_sync(~0u, s, o);
            if (t >= o) s += y;
        }
        wsum[t] = s;
    }
    __syncthreads();
    int off = (t >= 32) ? wsum[(t >> 5) - 1] : 0;
    int incl = x + off;
    if (i < N_NODES) g_rowstart[i] = incl - v;
    if (t == 1023) g_bsum[b] = incl;
}

__global__ void scan_top() {
    __shared__ int s[128];
    int t = threadIdx.x;
    int mine = (t < NBLK) ? g_bsum[t] : 0;
    s[t] = mine;
    __syncthreads();
#pragma unroll
    for (int o = 1; o < 128; o <<= 1) {
        int v = (t >= o) ? s[t - o] : 0;
        __syncthreads();
        s[t] += v;
        __syncthreads();
    }
    g_bsum[t] = s[t] - mine;
}

// ---------------------------------------------------------------------------
// Atomic-free CSR fill: 4 edges/thread, int4 loads.
// ---------------------------------------------------------------------------
__global__ void fill_csr(const int* __restrict__ esrc,
                         const int* __restrict__ edst) {
    int gi = blockIdx.x * blockDim.x + threadIdx.x;
    if (gi >= E4) return;
    int4 d4 = ((const int4*)edst)[gi];
    int4 s4 = ((const int4*)esrc)[gi];
    int4 r4 = ((const int4*)g_rank)[gi];
    g_csr[g_rowstart[d4.x] + g_bsum[d4.x >> 10] + r4.x] = s4.x;
    g_csr[g_rowstart[d4.y] + g_bsum[d4.y >> 10] + r4.y] = s4.y;
    g_csr[g_rowstart[d4.z] + g_bsum[d4.z >> 10] + r4.z] = s4.z;
    g_csr[g_rowstart[d4.w] + g_bsum[d4.w >> 10] + r4.w] = s4.w;
}

// ---------------------------------------------------------------------------
// Segmented gather-mean (R11 form — FROZEN): one warp per dst node, fp16
// depth-2 tree over 4 edges, scalar independent index loads, fp32 acc.
// ---------------------------------------------------------------------------
__global__ void __launch_bounds__(256)
gather_mean16() {
    int gtid = blockIdx.x * blockDim.x + threadIdx.x;
    int v    = gtid >> 5;
    int lane = threadIdx.x & 31;
    if (v >= N_NODES) return;

    int deg = g_deg[v];
    int rs  = g_rowstart[v] + g_bsum[v >> 10];
    int re  = rs + deg;

    const __half2* hb = g_h16 + lane * 2;   // lane's 2 half2 columns

    float2 f01 = make_float2(0.f, 0.f);
    float2 f23 = make_float2(0.f, 0.f);

    int i = rs;
    for (; i + 3 < re; i += 4) {
        int s0 = g_csr[i], s1 = g_csr[i + 1], s2 = g_csr[i + 2], s3 = g_csr[i + 3];
        uint2 u0 = *(const uint2*)(hb + (size_t)s0 * 64);
        uint2 u1 = *(const uint2*)(hb + (size_t)s1 * 64);
        uint2 u2 = *(const uint2*)(hb + (size_t)s2 * 64);
        uint2 u3 = *(const uint2*)(hb + (size_t)s3 * 64);
        __half2 ax = __hadd2(
            __hadd2(*reinterpret_cast<__half2*>(&u0.x), *reinterpret_cast<__half2*>(&u1.x)),
            __hadd2(*reinterpret_cast<__half2*>(&u2.x), *reinterpret_cast<__half2*>(&u3.x)));
        __half2 ay = __hadd2(
            __hadd2(*reinterpret_cast<__half2*>(&u0.y), *reinterpret_cast<__half2*>(&u1.y)),
            __hadd2(*reinterpret_cast<__half2*>(&u2.y), *reinterpret_cast<__half2*>(&u3.y)));
        float2 fx = __half22float2(ax);
        float2 fy = __half22float2(ay);
        f01.x += fx.x; f01.y += fx.y;
        f23.x += fy.x; f23.y += fy.y;
    }
    for (; i < re; i++) {
        int s0 = g_csr[i];
        uint2 u0 = *(const uint2*)(hb + (size_t)s0 * 64);
        float2 fx = __half22float2(*reinterpret_cast<__half2*>(&u0.x));
        float2 fy = __half22float2(*reinterpret_cast<__half2*>(&u0.y));
        f01.x += fx.x; f01.y += fx.y;
        f23.x += fy.x; f23.y += fy.y;
    }

    float inv = 1.0f / (float)max(deg, 1);
    __half2 p0 = __floats2half2_rn(f01.x * inv, f01.y * inv);
    __half2 p1 = __floats2half2_rn(f23.x * inv, f23.y * inv);
    uint2 u;
    u.x = *reinterpret_cast<uint32_t*>(&p0);
    u.y = *reinterpret_cast<uint32_t*>(&p1);
    *(uint2*)(g_c16 + (size_t)v * 64 + lane * 2) = u;
}

// ---------------------------------------------------------------------------
// fp16 GEMM, single-term A and W (exact R11 version).
// Block: 256 thr (8 warps), tile M=128 N=128, 4 K-chunks of 64. 2 blocks/SM.
// ---------------------------------------------------------------------------
#define SMW     0         // 4 chunks x 16KB = 65536 (reused for output stage)
#define SMA     65536     // 16KB
#define SM_BIAS 81920
#define SM_SSQ  82432
#define SM_TOTAL 83456

__global__ void __launch_bounds__(256, 2)
gemm_mma(const float* __restrict__ bias, float* __restrict__ out) {
    extern __shared__ char sm[];
    const uint32_t sb = smem_u32(sm);
    const int tid  = threadIdx.x;
    const int wid  = tid >> 5;
    const int lane = tid & 31;
    const int m0   = blockIdx.x * 128;
    const int mwarp = (wid >> 1) * 32;
    const int nwarp = (wid & 1) * 64;

    if (tid < 128) *(float*)(sm + SM_BIAS + tid * 4) = bias[tid];

    // ---- preload W fp16 (4 chunks, SW128) ----
    {
        int r = tid >> 1, half = tid & 1;
#pragma unroll
        for (int c = 0; c < 4; c++) {
#pragma unroll
            for (int j = 0; j < 4; j++) {
                uint32_t sw = SW128((uint32_t)(r * 128 + half * 64 + j * 16));
                *(uint4*)(sm + SMW + c * 16384 + sw) =
                    *(const uint4*)(g_Wf + r * K2 + c * 64 + half * 32 + j * 8);
            }
        }
    }

    const int r = tid >> 1, half = tid & 1;
    int mg = m0 + r;
    if (mg >= N_NODES) mg = N_NODES - 1;

    float acc[2][8][4];
#pragma unroll
    for (int mt = 0; mt < 2; mt++)
#pragma unroll
        for (int nt = 0; nt < 8; nt++)
#pragma unroll
            for (int q = 0; q < 4; q++) acc[mt][nt][q] = 0.0f;

    for (int ch = 0; ch < 4; ch++) {
        // ---- A chunk: fp16 direct copy, SW128 ----
        const __half2* asrc = ((ch < 2) ? g_h16 : g_c16) +
                              (size_t)mg * 64 + (ch & 1) * 32 + half * 16;
#pragma unroll
        for (int j = 0; j < 4; j++) {
            uint4 v = *(const uint4*)(asrc + j * 4);
            uint32_t sw = SW128((uint32_t)(r * 128 + half * 64 + j * 16));
            *(uint4*)(sm + SMA + sw) = v;
        }
        __syncthreads();

#pragma unroll
        for (int ks = 0; ks < 4; ks++) {
            const uint32_t kc2 = ks * 32;

            uint32_t af[2][4];
#pragma unroll
            for (int mt = 0; mt < 2; mt++) {
                uint32_t rowoff = mwarp + mt * 16 + (lane & 7) + ((lane >> 3) & 1) * 8;
                uint32_t colb   = kc2 + ((lane >> 4) << 4);
                uint32_t sw = SW128(rowoff * 128 + colb);
                ldsm_x4(af[mt], sb + SMA + sw);
            }
            uint32_t bw[4][4];
#pragma unroll
            for (int tp = 0; tp < 4; tp++) {
                uint32_t j = lane >> 3;
                uint32_t row = nwarp + tp * 16 + (lane & 7) + ((j >> 1) << 3);
                uint32_t colb = kc2 + ((j & 1) << 4);
                uint32_t sw = SW128(row * 128 + colb);
                ldsm_x4(bw[tp], sb + SMW + ch * 16384 + sw);
            }
#pragma unroll
            for (int mt = 0; mt < 2; mt++) {
#pragma unroll
                for (int nt = 0; nt < 8; nt++) {
                    uint32_t b0 = bw[nt >> 1][(nt & 1) * 2 + 0];
                    uint32_t b1 = bw[nt >> 1][(nt & 1) * 2 + 1];
                    mma_f16(acc[mt][nt], af[mt], b0, b1);
                }
            }
        }
        __syncthreads();
    }

    // ---- epilogue: bias -> ssq -> normalize -> relu -> staged store ----
#pragma unroll
    for (int mt = 0; mt < 2; mt++)
#pragma unroll
        for (int nt = 0; nt < 8; nt++) {
            float2 bb = *(const float2*)(sm + SM_BIAS +
                                         (nwarp + nt * 8 + (lane & 3) * 2) * 4);
            acc[mt][nt][0] += bb.x;
            acc[mt][nt][1] += bb.y;
            acc[mt][nt][2] += bb.x;
            acc[mt][nt][3] += bb.y;
        }

    float pp[2][2] = {{0.f, 0.f}, {0.f, 0.f}};
#pragma unroll
    for (int mt = 0; mt < 2; mt++)
#pragma unroll
        for (int nt = 0; nt < 8; nt++) {
            pp[mt][0] += acc[mt][nt][0] * acc[mt][nt][0] +
                         acc[mt][nt][1] * acc[mt][nt][1];
            pp[mt][1] += acc[mt][nt][2] * acc[mt][nt][2] +
                         acc[mt][nt][3] * acc[mt][nt][3];
        }
#pragma unroll
    for (int off = 1; off <= 2; off <<= 1) {
#pragma unroll
        for (int mt = 0; mt < 2; mt++) {
            pp[mt][0] += __shfl_xor_sync(~0u, pp[mt][0], off);
            pp[mt][1] += __shfl_xor_sync(~0u, pp[mt][1], off);
        }
    }
    if ((lane & 3) == 0) {
#pragma unroll
        for (int mt = 0; mt < 2; mt++)
#pragma unroll
            for (int hh = 0; hh < 2; hh++) {
                int row = mwarp + mt * 16 + (lane >> 2) + hh * 8;
                *(float*)(sm + SM_SSQ + (wid & 1) * 512 + row * 4) = pp[mt][hh];
            }
    }
    __syncthreads();

    float sc[2][2];
#pragma unroll
    for (int mt = 0; mt < 2; mt++)
#pragma unroll
        for (int hh = 0; hh < 2; hh++) {
            int row = mwarp + mt * 16 + (lane >> 2) + hh * 8;
            float s = *(const float*)(sm + SM_SSQ + row * 4) +
                      *(const float*)(sm + SM_SSQ + 512 + row * 4);
            sc[mt][hh] = 1.0f / fmaxf(sqrtf(s), 1e-12f);
        }
    __syncthreads();

    // stage relu'd rows into SMEM (reuse W region) then coalesced store
#pragma unroll
    for (int mt = 0; mt < 2; mt++) {
#pragma unroll
        for (int nt = 0; nt < 8; nt++) {
            int coln = nwarp + nt * 8 + (lane & 3) * 2;
            int row0 = mwarp + mt * 16 + (lane >> 2);
            int row1 = row0 + 8;
            float2 v0, v1;
            v0.x = fmaxf(acc[mt][nt][0] * sc[mt][0], 0.0f);
            v0.y = fmaxf(acc[mt][nt][1] * sc[mt][0], 0.0f);
            v1.x = fmaxf(acc[mt][nt][2] * sc[mt][1], 0.0f);
            v1.y = fmaxf(acc[mt][nt][3] * sc[mt][1], 0.0f);
            *(float2*)(sm + row0 * 512 + ((coln * 4) ^ ((row0 & 7) << 4))) = v0;
            *(float2*)(sm + row1 * 512 + ((coln * 4) ^ ((row1 & 7) << 4))) = v1;
        }
    }
    __syncthreads();

#pragma unroll
    for (int i = 0; i < 16; i++) {
        int idx = tid + i * 256;
        int rr = idx >> 5;
        int p  = idx & 31;
        int mgl = m0 + rr;
        if (mgl < N_NODES) {
            float4 o = *(const float4*)(sm + rr * 512 + ((p * 16) ^ ((rr & 7) << 4)));
            *(float4*)(out + (size_t)mgl * D + p * 4) = o;
        }
    }
}

// ---------------------------------------------------------------------------
extern "C" void kernel_launch(void* const* d_in, const int* in_sizes, int n_in,
                              void* d_out, int out_size) {
    const float* h    = (const float*)d_in[0];
    const float* W    = (const float*)d_in[1];
    const float* bias = (const float*)d_in[2];
    const int*   esrc = (const int*)d_in[3];
    const int*   edst = (const int*)d_in[4];
    float*       out  = (float*)d_out;

    void* p_deg = nullptr;
    cudaGetSymbolAddress(&p_deg, g_deg);
    cudaMemsetAsync(p_deg, 0, sizeof(int) * N_NODES, 0);

    cudaFuncSetAttribute(gemm_mma, cudaFuncAttributeMaxDynamicSharedMemorySize,
                         SM_TOTAL);

    prep_hist<<<3291, 256>>>(W, h, edst);
    scan_blocks<<<NBLK, 1024>>>();
    scan_top<<<1, 128>>>();
    fill_csr<<<(E4 + 255) / 256, 256>>>(esrc, edst);
    gather_mean16<<<(N_NODES * 32 + 255) / 256, 256>>>();
    gemm_mma<<<(N_NODES + 127) / 128, 256, SM_TOTAL>>>(bias, out);
}